// round 1
// baseline (speedup 1.0000x reference)
#include <cuda_runtime.h>
#include <cstdint>
#include <cstddef>

// Problem constants (fixed by the dataset)
#define B_  32
#define N_  1024
#define D_  128
#define C_  16
// P*P = 16, Hg = 32, out image 128x128 per (b,c)

// Tiling
#define NT      128   // n rows per block
#define THREADS 256   // thread = (n_local 0..127, p-half 0..1)
#define XPAD    4     // shared row pad (floats) for conflict-free LDS.128

// Shared layout (floats)
#define SX_OFF    0                   // [128][132]
#define SW_OFF    (128 * (D_ + XPAD)) // 16896: [16][128]
#define SCBM_OFF  (SW_OFF + 16 * D_)  // 18944: [16][16]
#define SMASK_OFF (SCBM_OFF + 256)    // 19200: [16]
#define SMEM_FLOATS (SMASK_OFF + 16)  // 19216
#define SMEM_BYTES  (SMEM_FLOATS * 4) // 76864

__device__ __forceinline__ uint32_t smem_u32(const void* p) {
    return (uint32_t)__cvta_generic_to_shared(p);
}

__global__ void __launch_bounds__(THREADS, 2)
QueryBasedDecoder_37546604102322_kernel(
    const float* __restrict__ x,     // [B, N, D]
    const float* __restrict__ pmask, // [B, C]
    const float* __restrict__ emb,   // [256, D] (only first C rows used)
    const float* __restrict__ W,     // [16, D]
    const float* __restrict__ bias,  // [16]
    float* __restrict__ out)         // [B, C, 128, 128]
{
    extern __shared__ float sm[];
    float* sx    = sm + SX_OFF;
    float* sw    = sm + SW_OFF;
    float* scbm  = sm + SCBM_OFF;
    float* smask = sm + SMASK_OFF;

    const int b  = blockIdx.y;
    const int n0 = blockIdx.x * NT;
    const int t  = threadIdx.x;

    // ---- Stage x tile (128 rows x 128 floats, contiguous 64KB in GMEM) via cp.async
    //      into padded shared rows (132 floats) ----
    const float4* gx = reinterpret_cast<const float4*>(x + ((size_t)b * N_ + n0) * D_);
    #pragma unroll
    for (int i = 0; i < 16; ++i) {
        int k = t + THREADS * i;                 // chunk id 0..4095 (row = k>>5, col16 = k&31)
        uint32_t dst = smem_u32(sx + (k >> 5) * (D_ + XPAD) + (k & 31) * 4);
        asm volatile("cp.async.cg.shared.global [%0], [%1], 16;\n"
                     :: "r"(dst), "l"(gx + k));
    }
    // ---- Stage W (16x128 floats = 512 chunks) ----
    const float4* gw = reinterpret_cast<const float4*>(W);
    #pragma unroll
    for (int i = 0; i < 2; ++i) {
        int k = t + THREADS * i;
        uint32_t dst = smem_u32(sw + k * 4);
        asm volatile("cp.async.cg.shared.global [%0], [%1], 16;\n"
                     :: "r"(dst), "l"(gw + k));
    }
    asm volatile("cp.async.commit_group;\n");

    // ---- Channel table, overlapped with the async copies:
    //      cbm[c][p] = (emb[c]·W[p] + bias[p]) * mask[b][c]  (one entry per thread) ----
    {
        const int c = t >> 4, p = t & 15;
        const float4* ev = reinterpret_cast<const float4*>(emb + (size_t)c * D_);
        const float4* wv = reinterpret_cast<const float4*>(W + (size_t)p * D_);
        float s = 0.f;
        #pragma unroll
        for (int i = 0; i < 32; ++i) {
            float4 a = ev[i], w4 = wv[i];
            s = fmaf(a.x, w4.x, s);
            s = fmaf(a.y, w4.y, s);
            s = fmaf(a.z, w4.z, s);
            s = fmaf(a.w, w4.w, s);
        }
        float m = pmask[b * C_ + c];
        scbm[t] = (s + bias[p]) * m;
        if (p == 0) smask[c] = m;
    }

    asm volatile("cp.async.wait_group 0;\n");
    __syncthreads();

    // ---- Main dot products: xa[n][p] for this thread's (n_local, 8 p's) ----
    const int nl   = t & 127;
    const int half = t >> 7;                     // 0: p=0..7, 1: p=8..15
    const float* xr = sx + nl * (D_ + XPAD);
    const float* wr = sw + half * 8 * D_;

    float acc[8];
    #pragma unroll
    for (int j = 0; j < 8; ++j) acc[j] = 0.f;

    #pragma unroll
    for (int d4 = 0; d4 < 32; ++d4) {
        float4 xv = *reinterpret_cast<const float4*>(xr + d4 * 4);
        #pragma unroll
        for (int j = 0; j < 8; ++j) {
            float4 wv = *reinterpret_cast<const float4*>(wr + j * D_ + d4 * 4);
            acc[j] = fmaf(xv.x, wv.x, acc[j]);
            acc[j] = fmaf(xv.y, wv.y, acc[j]);
            acc[j] = fmaf(xv.z, wv.z, acc[j]);
            acc[j] = fmaf(xv.w, wv.w, acc[j]);
        }
    }

    // ---- Epilogue: out[b][c][hg*4+pr][wg*4+pc] = acc*mask + cbm  (2x float4 per c) ----
    const int n  = n0 + nl;
    const int hg = n >> 5, wg = n & 31;
    float* ob = out + (size_t)b * (C_ * 128 * 128)
                    + (hg * 4 + half * 2) * 128 + wg * 4;

    #pragma unroll
    for (int c = 0; c < C_; ++c) {
        float m = smask[c];
        float4 cb0 = *reinterpret_cast<const float4*>(scbm + c * 16 + half * 8);
        float4 cb1 = *reinterpret_cast<const float4*>(scbm + c * 16 + half * 8 + 4);
        float4 lo, hi;
        lo.x = fmaf(acc[0], m, cb0.x);
        lo.y = fmaf(acc[1], m, cb0.y);
        lo.z = fmaf(acc[2], m, cb0.z);
        lo.w = fmaf(acc[3], m, cb0.w);
        hi.x = fmaf(acc[4], m, cb1.x);
        hi.y = fmaf(acc[5], m, cb1.y);
        hi.z = fmaf(acc[6], m, cb1.z);
        hi.w = fmaf(acc[7], m, cb1.w);
        float* o = ob + c * (128 * 128);
        *reinterpret_cast<float4*>(o)       = lo;   // row hg*4 + half*2
        *reinterpret_cast<float4*>(o + 128) = hi;   // row hg*4 + half*2 + 1
    }
}

extern "C" void kernel_launch(void* const* d_in, const int* in_sizes, int n_in,
                              void* d_out, int out_size)
{
    const float* x    = (const float*)d_in[0];  // [32,1024,128]
    const float* pm   = (const float*)d_in[1];  // [32,16]
    const float* emb  = (const float*)d_in[2];  // [256,128]
    const float* W    = (const float*)d_in[3];  // [16,128]
    const float* bias = (const float*)d_in[4];  // [16]
    float* out        = (float*)d_out;          // [32,16,128,128]

    cudaFuncSetAttribute(QueryBasedDecoder_37546604102322_kernel,
                         cudaFuncAttributeMaxDynamicSharedMemorySize, SMEM_BYTES);

    dim3 grid(N_ / NT, B_);   // (8, 32) = 256 blocks
    dim3 block(THREADS);
    QueryBasedDecoder_37546604102322_kernel<<<grid, block, SMEM_BYTES>>>(
        x, pm, emb, W, bias, out);
}